// round 1
// baseline (speedup 1.0000x reference)
#include <cuda_runtime.h>

// ---------------------------------------------------------------------------
// ContrastiveCRFLoss — B200/GB300 (sm_100a)
//
// out[n,a,b] = -( sum_k C[n,k,a]*C[n,k,b] ) *
//              ( 10*exp(-cd(a,b) - gd(n,a,b)/0.3) + 3*exp(-10*cd(a,b)) )
// cd(a,b) = (r_a-r_b)^2 + (c_a-c_b)^2           (batch independent)
// gd(n,a,b) = sum_ch (G[n,ch,a]-G[n,ch,b])^2    (3 channels)
//
// Phase 1: gather the 1000 sampled columns of clusters/guidance into padded
//          device-global scratch (L2-resident afterwards).
// Phase 2: tiled 64x64 GEMM-like kernel, 256 threads, 4x4 micro-tile per
//          thread, packed fma.rn.f32x2 for the 27-term dot product, coord
//          exponentials precomputed per tile and reused across 8 batches.
// ---------------------------------------------------------------------------

#define NB    32          // batches
#define KC    27          // cluster channels
#define CG    3           // guidance channels
#define NS    1000        // samples
#define NPAD  1024        // padded sample stride
#define HW    256         // image H=W
#define TILE  64
#define NTILE ((NS + TILE - 1) / TILE)   // 16
#define BSPLIT 4                          // grid.z; batches per CTA = 8
#define BPER   (NB / BSPLIT)

// ---- device scratch (static allocation: allowed under _HX_ENFORCE) --------
__device__ float d_selC[NB * KC * NPAD];   // gathered clusters [n][k][s]
__device__ float d_selG[NB * CG * NPAD];   // gathered guidance [n][ch][s]
__device__ float d_ga2 [NB * NPAD];        // per-point guidance squared norm
__device__ float d_rf  [NPAD];             // row coord as float
__device__ float d_cf  [NPAD];             // col coord as float

// ---- packed fp32x2 helpers (Blackwell) ------------------------------------
typedef unsigned long long ull;

__device__ __forceinline__ ull ffma2(ull a, ull b, ull c) {
    ull d;
    asm("fma.rn.f32x2 %0, %1, %2, %3;" : "=l"(d) : "l"(a), "l"(b), "l"(c));
    return d;
}
__device__ __forceinline__ ull pack2(float lo, float hi) {
    ull d;
    asm("mov.b64 %0, {%1, %2};" : "=l"(d) : "f"(lo), "f"(hi));
    return d;
}
__device__ __forceinline__ float2 unpack2(ull v) {
    float2 r;
    asm("mov.b64 {%0, %1}, %2;" : "=f"(r.x), "=f"(r.y) : "l"(v));
    return r;
}

// ---------------------------------------------------------------------------
// Gather kernels
// ---------------------------------------------------------------------------
__global__ void gather_clusters_k(const float* __restrict__ clusters,
                                  const int*   __restrict__ coords) {
    int idx = blockIdx.x * blockDim.x + threadIdx.x;
    if (idx >= NB * KC * NS) return;
    int s  = idx % NS;
    int nk = idx / NS;             // n*27 + k
    int r = coords[s];
    int c = coords[NS + s];
    d_selC[nk * NPAD + s] = clusters[((size_t)nk * HW + r) * HW + c];
}

__global__ void gather_guidance_k(const float* __restrict__ guidance,
                                  const int*   __restrict__ coords) {
    int idx = blockIdx.x * blockDim.x + threadIdx.x;
    if (idx >= NB * NS) return;
    int s = idx % NS;
    int n = idx / NS;
    int r = coords[s];
    int c = coords[NS + s];
    float g0 = guidance[(((size_t)n * CG + 0) * HW + r) * HW + c];
    float g1 = guidance[(((size_t)n * CG + 1) * HW + r) * HW + c];
    float g2 = guidance[(((size_t)n * CG + 2) * HW + r) * HW + c];
    d_selG[(n * CG + 0) * NPAD + s] = g0;
    d_selG[(n * CG + 1) * NPAD + s] = g1;
    d_selG[(n * CG + 2) * NPAD + s] = g2;
    d_ga2[n * NPAD + s] = g0 * g0 + g1 * g1 + g2 * g2;
    if (idx < NS) {                // n == 0 threads also stash float coords
        d_rf[idx] = (float)r;
        d_cf[idx] = (float)c;
    }
}

// ---------------------------------------------------------------------------
// Main kernel: grid (b_tiles=16, a_tiles=16, BSPLIT), 256 threads.
// Thread (tx, ty): tx along contiguous b (4 cols), ty along a (4 rows).
// ---------------------------------------------------------------------------
__global__ void __launch_bounds__(256, 2)
crf_main_k(float* __restrict__ out) {
    __shared__ float sCa[KC][TILE];
    __shared__ float sCb[KC][TILE];
    __shared__ float sGa[CG][TILE];
    __shared__ float sGb[CG][TILE];
    __shared__ float sga2[TILE];
    __shared__ float sgb2[TILE];
    __shared__ float sAr[TILE], sAc[TILE], sBr[TILE], sBc[TILE];

    const int tid = threadIdx.x;
    const int tx  = tid & 15;      // b direction
    const int ty  = tid >> 4;      // a direction
    const int Bb  = blockIdx.x * TILE;   // b tile base (contiguous in out)
    const int Ab  = blockIdx.y * TILE;   // a tile base

    if (tid < TILE) {
        int ia = min(Ab + tid, NS - 1);
        int ib = min(Bb + tid, NS - 1);
        sAr[tid] = d_rf[ia];  sAc[tid] = d_cf[ia];
        sBr[tid] = d_rf[ib];  sBc[tid] = d_cf[ib];
    }
    __syncthreads();

    const int a0 = ty * 4;
    const int b0 = tx * 4;

    // Batch-independent coordinate kernels, computed once, reused 8x.
    // E1  = W1 * exp(-cd / (2*ALPHA)) = 10 * exp(-cd)
    // E2w = W2 * exp(-cd / (2*GAMMA)) =  3 * exp(-10*cd)
    float E1[4][4], E2w[4][4];
    #pragma unroll
    for (int i = 0; i < 4; i++) {
        float ar = sAr[a0 + i], ac = sAc[a0 + i];
        #pragma unroll
        for (int j = 0; j < 4; j++) {
            float dr = ar - sBr[b0 + j];
            float dc = ac - sBc[b0 + j];
            float cd = dr * dr + dc * dc;
            E1[i][j]  = 10.0f * __expf(-cd);
            E2w[i][j] =  3.0f * __expf(-10.0f * cd);
        }
    }

    const bool bvalid = (Bb + b0) < NS;          // b groups never straddle 1000
    const float inv2beta = -3.33333333f;          // -1/(2*0.15)

    for (int nb = 0; nb < BPER; nb++) {
        const int n = blockIdx.z * BPER + nb;

        __syncthreads();   // previous iteration's epilogue reads are done

        // ---- stage this batch's tile columns into SMEM ----
        const float* Cbase = d_selC + (size_t)n * KC * NPAD;
        for (int t = tid; t < KC * TILE; t += 256) {
            int k = t >> 6, i = t & 63;
            sCa[k][i] = Cbase[k * NPAD + min(Ab + i, NS - 1)];
            sCb[k][i] = Cbase[k * NPAD + min(Bb + i, NS - 1)];
        }
        const float* Gbase = d_selG + (size_t)n * CG * NPAD;
        if (tid < CG * TILE) {
            int ch = tid >> 6, i = tid & 63;
            sGa[ch][i] = Gbase[ch * NPAD + min(Ab + i, NS - 1)];
            sGb[ch][i] = Gbase[ch * NPAD + min(Bb + i, NS - 1)];
        }
        if (tid < TILE) {
            sga2[tid] = d_ga2[n * NPAD + min(Ab + tid, NS - 1)];
            sgb2[tid] = d_ga2[n * NPAD + min(Bb + tid, NS - 1)];
        }
        __syncthreads();

        // ---- 27-term gram dot, packed f32x2: 8 FFMA2 per k-step ----
        ull acc[4][2];
        #pragma unroll
        for (int i = 0; i < 4; i++) { acc[i][0] = 0ull; acc[i][1] = 0ull; }

        #pragma unroll
        for (int k = 0; k < KC; k++) {
            float4 a4 = *(const float4*)&sCa[k][a0];
            float4 b4 = *(const float4*)&sCb[k][b0];
            ull b01 = pack2(b4.x, b4.y);
            ull b23 = pack2(b4.z, b4.w);
            float av[4] = {a4.x, a4.y, a4.z, a4.w};
            #pragma unroll
            for (int i = 0; i < 4; i++) {
                ull ad = pack2(av[i], av[i]);
                acc[i][0] = ffma2(ad, b01, acc[i][0]);
                acc[i][1] = ffma2(ad, b23, acc[i][1]);
            }
        }

        // ---- epilogue: guidance kernel + combine + store ----
        float gaCh[CG][4], gbCh[CG][4];
        #pragma unroll
        for (int ch = 0; ch < CG; ch++) {
            float4 t = *(const float4*)&sGa[ch][a0];
            gaCh[ch][0] = t.x; gaCh[ch][1] = t.y; gaCh[ch][2] = t.z; gaCh[ch][3] = t.w;
            float4 u = *(const float4*)&sGb[ch][b0];
            gbCh[ch][0] = u.x; gbCh[ch][1] = u.y; gbCh[ch][2] = u.z; gbCh[ch][3] = u.w;
        }
        float4 ga2q = *(const float4*)&sga2[a0];
        float4 gb2q = *(const float4*)&sgb2[b0];
        float ga2a[4] = {ga2q.x, ga2q.y, ga2q.z, ga2q.w};
        float gb2a[4] = {gb2q.x, gb2q.y, gb2q.z, gb2q.w};

        size_t outBase = ((size_t)n * NS + (Ab + a0)) * NS + (Bb + b0);

        #pragma unroll
        for (int i = 0; i < 4; i++) {
            float2 d01 = unpack2(acc[i][0]);
            float2 d23 = unpack2(acc[i][1]);
            float dots[4] = {d01.x, d01.y, d23.x, d23.y};
            float4 res;
            float* rp = (float*)&res;
            #pragma unroll
            for (int j = 0; j < 4; j++) {
                float dot3 = gaCh[0][i] * gbCh[0][j];
                dot3 = fmaf(gaCh[1][i], gbCh[1][j], dot3);
                dot3 = fmaf(gaCh[2][i], gbCh[2][j], dot3);
                float gd = ga2a[i] + gb2a[j] - 2.0f * dot3;
                float eg = __expf(gd * inv2beta);
                float s  = fmaf(E1[i][j], eg, E2w[i][j]);
                rp[j] = -dots[j] * s;
            }
            int arow = Ab + a0 + i;
            if (bvalid && arow < NS) {
                *(float4*)(out + outBase + (size_t)i * NS) = res;
            }
        }
    }
}

// ---------------------------------------------------------------------------
extern "C" void kernel_launch(void* const* d_in, const int* in_sizes, int n_in,
                              void* d_out, int out_size) {
    const float* guidance = (const float*)d_in[0];
    const float* clusters = (const float*)d_in[1];
    const int*   coords   = (const int*)d_in[2];
    float* out = (float*)d_out;

    gather_clusters_k<<<(NB * KC * NS + 255) / 256, 256>>>(clusters, coords);
    gather_guidance_k<<<(NB * NS + 255) / 256, 256>>>(guidance, coords);

    dim3 grid(NTILE, NTILE, BSPLIT);
    crf_main_k<<<grid, 256>>>(out);
}